// round 1
// baseline (speedup 1.0000x reference)
#include <cuda_runtime.h>

#define H 64
#define NV_MAX 100000

// scratch (device globals — no allocation allowed)
__device__ float g_agg[(size_t)NV_MAX * H];
__device__ float g_deg[NV_MAX];

__global__ void zero_kernel(int nv) {
    int i = blockIdx.x * blockDim.x + threadIdx.x;
    int n4 = nv * (H / 4);
    if (i < n4) reinterpret_cast<float4*>(g_agg)[i] = make_float4(0.f, 0.f, 0.f, 0.f);
    if (i < nv) g_deg[i] = 0.f;
}

// 16 threads per edge; each handles one float4 chunk of the 64-float row.
__global__ void scatter_kernel(const float4* __restrict__ x,
                               const int* __restrict__ src,
                               const int* __restrict__ dst, int E) {
    int i = blockIdx.x * blockDim.x + threadIdx.x;
    int total = E * 16;
    if (i >= total) return;
    int e = i >> 4;
    int c = i & 15;
    int s = __ldg(&src[e]);
    int d = __ldg(&dst[e]);
    float4 v = x[(long)s * 16 + c];
    float* p = &g_agg[(long)d * H + c * 4];
    asm volatile("red.global.add.v4.f32 [%0], {%1,%2,%3,%4};"
                 :: "l"(p), "f"(v.x), "f"(v.y), "f"(v.z), "f"(v.w) : "memory");
    if (c == 0) atomicAdd(&g_deg[d], 1.0f);
}

// 256 threads, 4 rows per pass. Thread (g = tid/64 selects row, h = tid%64
// selects output column). W row h lives in registers for the whole kernel.
__global__ void __launch_bounds__(256, 2)
finalize_kernel(const float* __restrict__ W, const float* __restrict__ b,
                const float* __restrict__ gamma, const float* __restrict__ beta,
                float* __restrict__ out, int nv) {
    const int tid = threadIdx.x;
    const int g = tid >> 6;
    const int h = tid & 63;
    const int wid = tid >> 5;

    // Load W row h into registers (one-time; small, L2-cached).
    float Wr[64];
#pragma unroll
    for (int k4 = 0; k4 < 16; k4++) {
        float4 w = reinterpret_cast<const float4*>(W)[h * 16 + k4];
        Wr[4 * k4 + 0] = w.x;
        Wr[4 * k4 + 1] = w.y;
        Wr[4 * k4 + 2] = w.z;
        Wr[4 * k4 + 3] = w.w;
    }
    const float bh = b[h];
    const float gh = gamma[h];
    const float beh = beta[h];

    __shared__ __align__(16) float s_sf[4][64];
    __shared__ float red1[8], red2[8];

    for (int base = blockIdx.x * 4; base < nv; base += gridDim.x * 4) {
        int row = base + g;
        __syncthreads();  // protect s_sf / red reuse
        if (row < nv) s_sf[g][h] = g_agg[(long)row * H + h];
        __syncthreads();

        float v = 0.f;
        if (row < nv) {
            const float4* sv = reinterpret_cast<const float4*>(s_sf[g]);
            float y = 0.f;
#pragma unroll
            for (int k4 = 0; k4 < 16; k4++) {
                float4 sk = sv[k4];
                y = fmaf(Wr[4 * k4 + 0], sk.x, y);
                y = fmaf(Wr[4 * k4 + 1], sk.y, y);
                y = fmaf(Wr[4 * k4 + 2], sk.z, y);
                y = fmaf(Wr[4 * k4 + 3], sk.w, y);
            }
            float dg = g_deg[row];
            float inv = 1.0f / (dg + 1e-6f);
            v = (y + dg * bh) * inv;
            v = fmaxf(v, 0.f);
        }

        // LayerNorm reduction over the 64 lanes of this row (2 warps).
        float s1 = v, s2 = v * v;
#pragma unroll
        for (int off = 16; off > 0; off >>= 1) {
            s1 += __shfl_xor_sync(0xffffffffu, s1, off);
            s2 += __shfl_xor_sync(0xffffffffu, s2, off);
        }
        if ((tid & 31) == 0) { red1[wid] = s1; red2[wid] = s2; }
        __syncthreads();
        float sum = s1 + red1[wid ^ 1];
        float sumsq = s2 + red2[wid ^ 1];

        if (row < nv) {
            float mu = sum * (1.0f / 64.0f);
            float var = sumsq * (1.0f / 64.0f) - mu * mu;
            float o = (v - mu) * rsqrtf(var + 1e-5f) * gh + beh;
            out[(long)row * H + h] = o;
        }
    }
}

extern "C" void kernel_launch(void* const* d_in, const int* in_sizes, int n_in,
                              void* d_out, int out_size) {
    const float* x_con = (const float*)d_in[0];
    const int* src = (const int*)d_in[1];
    const int* dst = (const int*)d_in[2];
    // num_var may or may not be materialized as an input; locate W robustly.
    int wi = 3;
    if (n_in >= 8 || in_sizes[3] != H * H) {
        // prefer the index whose size is H*H
        for (int i = 3; i < n_in; i++) {
            if (in_sizes[i] == H * H) { wi = i; break; }
        }
    }
    const float* W = (const float*)d_in[wi];
    const float* b = (const float*)d_in[wi + 1];
    const float* gamma = (const float*)d_in[wi + 2];
    const float* beta = (const float*)d_in[wi + 3];

    int E = in_sizes[1];
    int nv = out_size / H;

    // 1. zero scratch
    {
        int n = nv * (H / 4);
        int blocks = (n + 255) / 256;
        zero_kernel<<<blocks, 256>>>(nv);
    }
    // 2. scatter-add raw x rows + degree
    {
        long total = (long)E * 16;
        int blocks = (int)((total + 255) / 256);
        scatter_kernel<<<blocks, 256>>>((const float4*)x_con, src, dst, E);
    }
    // 3. GEMV + normalize + ReLU + LayerNorm
    {
        int blocks = (nv + 3) / 4;
        if (blocks > 1480) blocks = 1480;
        finalize_kernel<<<blocks, 256>>>(W, b, gamma, beta, (float*)d_out, nv);
    }
}